// round 11
// baseline (speedup 1.0000x reference)
#include <cuda_runtime.h>
#include <cuda_bf16.h>
#include <math.h>
#include <stdint.h>

#define DIM 512
#define P_MAX 2048
#define R_MAX 65536
#define BM 128
#define BN 128
#define BK 64                 // bf16 elems per chunk = 128 bytes/row
#define NCHUNK (DIM / BK)     // 8
#define STAGES 3
#define A_BYTES (BM * 128)    // 16384
#define B_BYTES (BN * 128)    // 16384
#define STAGE_BYTES (A_BYTES + B_BYTES)      // 32768
#define SMEM_BYTES (STAGES * STAGE_BYTES)    // 98304 -> 2 CTAs/SM

// Scratch (no allocations allowed)
__device__ __nv_bfloat16 g_A[P_MAX * DIM];   // 2 MB
__device__ __nv_bfloat16 g_B[R_MAX * DIM];   // 64 MB
__device__ float g_xn[P_MAX];
__device__ float g_yn[R_MAX];
__device__ unsigned int g_min_bits;

// ---------------- helpers ----------------
__device__ __forceinline__ unsigned int enc_f(float f) {
    unsigned int u = __float_as_uint(f);
    return (u & 0x80000000u) ? ~u : (u | 0x80000000u);
}
__device__ __forceinline__ float dec_f(unsigned int u) {
    return (u & 0x80000000u) ? __uint_as_float(u & 0x7FFFFFFFu)
                             : __uint_as_float(~u);
}
__device__ __forceinline__ uint32_t smem_u32(const void* p) {
    uint32_t a;
    asm("{ .reg .u64 t; cvta.to.shared.u64 t, %1; cvt.u32.u64 %0, t; }"
        : "=r"(a) : "l"(p));
    return a;
}
__device__ __forceinline__ void cp16(uint32_t dst, const void* src) {
    asm volatile("cp.async.cg.shared.global [%0], [%1], 16;"
                 :: "r"(dst), "l"(src) : "memory");
}
__device__ __forceinline__ uint32_t swz(uint32_t off) {
    return off ^ ((off >> 3) & 0x70);   // SW128 pattern on 128B rows
}
__device__ __forceinline__ void ldsm_x4(uint32_t& r0, uint32_t& r1,
                                        uint32_t& r2, uint32_t& r3,
                                        uint32_t addr) {
    asm volatile("ldmatrix.sync.aligned.m8n8.x4.shared.b16 {%0,%1,%2,%3}, [%4];"
                 : "=r"(r0), "=r"(r1), "=r"(r2), "=r"(r3) : "r"(addr));
}
__device__ __forceinline__ void mma_bf16(float* c, const uint32_t* a,
                                         uint32_t b0, uint32_t b1) {
    asm volatile(
        "mma.sync.aligned.m16n8k16.row.col.f32.bf16.bf16.f32 "
        "{%0,%1,%2,%3}, {%4,%5,%6,%7}, {%8,%9}, {%0,%1,%2,%3};"
        : "+f"(c[0]), "+f"(c[1]), "+f"(c[2]), "+f"(c[3])
        : "r"(a[0]), "r"(a[1]), "r"(a[2]), "r"(a[3]), "r"(b0), "r"(b1));
}

// Load one K-chunk (A:128x64, B:128x64 bf16) into SW128-swizzled SMEM.
__device__ __forceinline__ void load_stage(uint32_t sbase, int s, int k0,
                                           int bm, int bn, int tid) {
    uint32_t a0 = sbase + s * STAGE_BYTES;
    uint32_t b0 = a0 + A_BYTES;
#pragma unroll
    for (int i = 0; i < 4; i++) {            // A: 1024 x 16B units
        int u = tid + i * 256;
        int row = u >> 3, c = u & 7;
        uint32_t sw = swz(row * 128 + c * 16);
        cp16(a0 + sw, g_A + (size_t)(bm + row) * DIM + k0 + c * 8);
    }
#pragma unroll
    for (int i = 0; i < 4; i++) {            // B: 1024 x 16B units
        int u = tid + i * 256;
        int row = u >> 3, c = u & 7;
        uint32_t sw = swz(row * 128 + c * 16);
        cp16(b0 + sw, g_B + (size_t)(bn + row) * DIM + k0 + c * 8);
    }
}

// Issue the cp.async group for flattened stream position `pos`
// (tile = bid + (pos/8)*ncta, chunk = pos%8, stage = pos%3).
// ALWAYS commits a group (possibly empty) so wait_group counts stay uniform.
__device__ __forceinline__ void issue_load(uint32_t sbase, int pos, int bid,
                                           int ncta, int nbn_sh, int ntiles,
                                           int tid) {
    int t = bid + (pos >> 3) * ncta;
    if (t < ntiles) {
        int bm = (t >> nbn_sh) * BM;
        int bn = (t & ((1 << nbn_sh) - 1)) * BN;
        load_stage(sbase, pos % 3, (pos & 7) * BK, bm, bn, tid);
    }
    asm volatile("cp.async.commit_group;" ::: "memory");
}

// ------------- kernel 0: convert to bf16, fp32 norms, reset min -------------
__global__ void prep_kernel(const float* __restrict__ x,
                            const float* __restrict__ y, int P, int R) {
    int warp = (blockIdx.x * blockDim.x + threadIdx.x) >> 5;
    int lane = threadIdx.x & 31;
    if (blockIdx.x == 0 && threadIdx.x == 0) g_min_bits = 0xFFFFFFFFu;
    if (warp >= P + R) return;
    const float4* src4;
    uint2* dst2;
    if (warp < P) {
        src4 = (const float4*)(x + (size_t)warp * DIM);
        dst2 = (uint2*)(g_A + (size_t)warp * DIM);
    } else {
        int r = warp - P;
        src4 = (const float4*)(y + (size_t)r * DIM);
        dst2 = (uint2*)(g_B + (size_t)r * DIM);
    }
    float acc = 0.f;
#pragma unroll
    for (int j = 0; j < 4; j++) {
        float4 v = src4[lane + j * 32];
        acc += v.x * v.x + v.y * v.y + v.z * v.z + v.w * v.w;
        __nv_bfloat162 lo = __floats2bfloat162_rn(v.x, v.y);
        __nv_bfloat162 hi = __floats2bfloat162_rn(v.z, v.w);
        uint2 u;
        u.x = *reinterpret_cast<unsigned int*>(&lo);
        u.y = *reinterpret_cast<unsigned int*>(&hi);
        dst2[lane + j * 32] = u;
    }
#pragma unroll
    for (int off = 16; off > 0; off >>= 1)
        acc += __shfl_xor_sync(0xFFFFFFFFu, acc, off);
    if (lane == 0) {
        if (warp < P) g_xn[warp] = acc;
        else          g_yn[warp - P] = acc;
    }
}

// ------------- kernel 1: persistent bf16 mma.sync GEMM + min reduction -------
// 128x128 tiles, 8 warps in 4(M) x 2(N), 32x64 per warp, 2 CTAs/SM.
// Persistent CTAs: the 3-stage cp.async ring runs continuously across tile
// boundaries (no pipeline drain between tiles, no wave transitions).
__global__ void __launch_bounds__(256, 2)
min_dist_mma_kernel(int nbn_sh, int ntiles) {
    extern __shared__ char smem[];
    uint32_t sbase = smem_u32(smem);
    const int tid = threadIdx.x;
    const int lane = tid & 31;
    const int warp = tid >> 5;
    const int wm = warp & 3;          // 0..3 : M direction (32 rows each)
    const int wn = warp >> 2;         // 0..1 : N direction (64 cols each)
    const int bid = blockIdx.x;
    const int ncta = gridDim.x;

    const int lrow = lane & 15;
    const int lcol = (lane >> 4) << 4;   // 0 or 16 bytes

    // Prefetch stream positions 0,1.
    issue_load(sbase, 0, bid, ncta, nbn_sh, ntiles, tid);
    issue_load(sbase, 1, bid, ncta, nbn_sh, ntiles, tid);

    int p = 0;   // flattened (tile, chunk) stream position
    for (int t = bid; t < ntiles; t += ncta) {
        const int bm = (t >> nbn_sh) * BM;
        const int bn = (t & ((1 << nbn_sh) - 1)) * BN;

        float acc[2][8][4];
#pragma unroll
        for (int i = 0; i < 2; i++)
#pragma unroll
            for (int j = 0; j < 8; j++)
#pragma unroll
                for (int r = 0; r < 4; r++) acc[i][j][r] = 0.f;

        for (int k = 0; k < NCHUNK; k++, p++) {
            asm volatile("cp.async.wait_group 1;" ::: "memory");
            __syncthreads();
            issue_load(sbase, p + 2, bid, ncta, nbn_sh, ntiles, tid);

            const uint32_t a0 = sbase + (p % 3) * STAGE_BYTES;
            const uint32_t b0 = a0 + A_BYTES;
#pragma unroll
            for (int kk = 0; kk < 4; kk++) {          // 4 x k16 steps per chunk
                const int colb = kk * 32 + lcol;
                uint32_t af[2][4];
#pragma unroll
                for (int mi = 0; mi < 2; mi++) {
                    int row = wm * 32 + mi * 16 + lrow;
                    ldsm_x4(af[mi][0], af[mi][1], af[mi][2], af[mi][3],
                            a0 + swz(row * 128 + colb));
                }
                uint32_t bf[8][2];
#pragma unroll
                for (int ni2 = 0; ni2 < 4; ni2++) {   // each x4 covers 2 n8 tiles
                    int row = wn * 64 + ni2 * 16 + lrow;
                    uint32_t r0, r1, r2, r3;
                    ldsm_x4(r0, r1, r2, r3, b0 + swz(row * 128 + colb));
                    bf[ni2 * 2 + 0][0] = r0; bf[ni2 * 2 + 0][1] = r2;
                    bf[ni2 * 2 + 1][0] = r1; bf[ni2 * 2 + 1][1] = r3;
                }
#pragma unroll
                for (int mi = 0; mi < 2; mi++)
#pragma unroll
                    for (int ni = 0; ni < 8; ni++)
                        mma_bf16(acc[mi][ni], af[mi], bf[ni][0], bf[ni][1]);
            }
        }

        // Epilogue: sq = xn + yn - 2*dot; norms straight from L2-hot globals
        // (no smem staging -> no extra barriers; loads for the next tile's
        // first chunks are already in flight).
        float m = 3.4e38f;
#pragma unroll
        for (int mi = 0; mi < 2; mi++) {
            float x0 = g_xn[bm + wm * 32 + mi * 16 + (lane >> 2)];
            float x1 = g_xn[bm + wm * 32 + mi * 16 + (lane >> 2) + 8];
#pragma unroll
            for (int ni = 0; ni < 8; ni++) {
                float2 y = *reinterpret_cast<const float2*>(
                    &g_yn[bn + wn * 64 + ni * 8 + (lane & 3) * 2]);
                m = fminf(m, fmaf(-2.0f, acc[mi][ni][0], x0 + y.x));
                m = fminf(m, fmaf(-2.0f, acc[mi][ni][1], x0 + y.y));
                m = fminf(m, fmaf(-2.0f, acc[mi][ni][2], x1 + y.x));
                m = fminf(m, fmaf(-2.0f, acc[mi][ni][3], x1 + y.y));
            }
        }
#pragma unroll
        for (int off = 16; off > 0; off >>= 1)
            m = fminf(m, __shfl_xor_sync(0xFFFFFFFFu, m, off));
        if (lane == 0) atomicMin(&g_min_bits, enc_f(m));
    }

    asm volatile("cp.async.wait_group 0;" ::: "memory");  // drain tail copies
}

// ------------- kernel 2: finalize -------------
__global__ void finalize_kernel(float* __restrict__ out) {
    out[0] = sqrtf(fmaxf(dec_f(g_min_bits), 0.0f));
}

extern "C" void kernel_launch(void* const* d_in, const int* in_sizes, int n_in,
                              void* d_out, int out_size) {
    const float* x = (const float*)d_in[0];  // [1, P, 512] fp32
    const float* y = (const float*)d_in[1];  // [1, R, 512] fp32
    int P = in_sizes[0] / DIM;
    int R = in_sizes[1] / DIM;

    int rows = P + R;  // one warp per row
    prep_kernel<<<(rows * 32 + 255) / 256, 256>>>(x, y, P, R);

    int nbn = R / BN;             // 512 (power of two for the fixed shape)
    int nbn_sh = 0;
    while ((1 << nbn_sh) < nbn) nbn_sh++;
    int ntiles = (P / BM) * nbn;  // 8192

    int sms = 148;
    cudaDeviceGetAttribute(&sms, cudaDevAttrMultiProcessorCount, 0);
    int ncta = sms * 2;           // exactly 2 CTAs/SM resident
    if (ncta > ntiles) ncta = ntiles;

    cudaFuncSetAttribute(min_dist_mma_kernel,
                         cudaFuncAttributeMaxDynamicSharedMemorySize, SMEM_BYTES);
    min_dist_mma_kernel<<<ncta, 256, SMEM_BYTES>>>(nbn_sh, ntiles);

    finalize_kernel<<<1, 1>>>((float*)d_out);
}

// round 12
// speedup vs baseline: 1.0771x; 1.0771x over previous
#include <cuda_runtime.h>
#include <cuda_bf16.h>
#include <math.h>
#include <stdint.h>

#define DIM 512
#define P_MAX 2048
#define R_MAX 65536
#define BM 128
#define BN 128
#define BK 64                 // bf16 elems per chunk = 128 bytes/row
#define NCHUNK (DIM / BK)     // 8
#define STAGES 3
#define A_BYTES (BM * 128)    // 16384
#define B_BYTES (BN * 128)    // 16384
#define STAGE_BYTES (A_BYTES + B_BYTES)          // 32768
#define SOFF_XN (STAGES * STAGE_BYTES)           // 98304
#define SOFF_YN (SOFF_XN + BM * 4)
#define SOFF_RED (SOFF_YN + BN * 4)              // 8 floats warp partials
#define SMEM_BYTES (SOFF_RED + 32)               // 99360 -> 2 CTAs/SM

// Scratch (no allocations allowed)
__device__ __nv_bfloat16 g_A[P_MAX * DIM];   // 2 MB
__device__ __nv_bfloat16 g_B[R_MAX * DIM];   // 64 MB
__device__ float g_xn[P_MAX];
__device__ float g_yn[R_MAX];
__device__ unsigned int g_min_bits;

// ---------------- helpers ----------------
__device__ __forceinline__ unsigned int enc_f(float f) {
    unsigned int u = __float_as_uint(f);
    return (u & 0x80000000u) ? ~u : (u | 0x80000000u);
}
__device__ __forceinline__ float dec_f(unsigned int u) {
    return (u & 0x80000000u) ? __uint_as_float(u & 0x7FFFFFFFu)
                             : __uint_as_float(~u);
}
__device__ __forceinline__ uint32_t smem_u32(const void* p) {
    uint32_t a;
    asm("{ .reg .u64 t; cvta.to.shared.u64 t, %1; cvt.u32.u64 %0, t; }"
        : "=r"(a) : "l"(p));
    return a;
}
__device__ __forceinline__ void cp16(uint32_t dst, const void* src) {
    asm volatile("cp.async.cg.shared.global [%0], [%1], 16;"
                 :: "r"(dst), "l"(src) : "memory");
}
__device__ __forceinline__ uint32_t swz(uint32_t off) {
    return off ^ ((off >> 3) & 0x70);   // SW128 pattern on 128B rows
}
__device__ __forceinline__ void ldsm_x4(uint32_t& r0, uint32_t& r1,
                                        uint32_t& r2, uint32_t& r3,
                                        uint32_t addr) {
    asm volatile("ldmatrix.sync.aligned.m8n8.x4.shared.b16 {%0,%1,%2,%3}, [%4];"
                 : "=r"(r0), "=r"(r1), "=r"(r2), "=r"(r3) : "r"(addr));
}
__device__ __forceinline__ void mma_bf16(float* c, const uint32_t* a,
                                         uint32_t b0, uint32_t b1) {
    asm volatile(
        "mma.sync.aligned.m16n8k16.row.col.f32.bf16.bf16.f32 "
        "{%0,%1,%2,%3}, {%4,%5,%6,%7}, {%8,%9}, {%0,%1,%2,%3};"
        : "+f"(c[0]), "+f"(c[1]), "+f"(c[2]), "+f"(c[3])
        : "r"(a[0]), "r"(a[1]), "r"(a[2]), "r"(a[3]), "r"(b0), "r"(b1));
}

// Load one K-chunk (A:128x64, B:128x64 bf16) into SW128-swizzled SMEM.
// 2048 x 16B units over 256 threads = 8 cp.async each.
__device__ __forceinline__ void load_stage(uint32_t sbase, int s, int k0,
                                           int bm, int bn, int tid) {
    uint32_t a0 = sbase + s * STAGE_BYTES;
    uint32_t b0 = a0 + A_BYTES;
#pragma unroll
    for (int i = 0; i < 4; i++) {            // A: 1024 units
        int u = tid + i * 256;
        int row = u >> 3, c = u & 7;
        uint32_t sw = swz(row * 128 + c * 16);
        cp16(a0 + sw, g_A + (size_t)(bm + row) * DIM + k0 + c * 8);
    }
#pragma unroll
    for (int i = 0; i < 4; i++) {            // B: 1024 units
        int u = tid + i * 256;
        int row = u >> 3, c = u & 7;
        uint32_t sw = swz(row * 128 + c * 16);
        cp16(b0 + sw, g_B + (size_t)(bn + row) * DIM + k0 + c * 8);
    }
}

// ------------- kernel 0: convert to bf16, fp32 norms, reset min -------------
__global__ void prep_kernel(const float* __restrict__ x,
                            const float* __restrict__ y, int P, int R) {
    int warp = (blockIdx.x * blockDim.x + threadIdx.x) >> 5;
    int lane = threadIdx.x & 31;
    if (blockIdx.x == 0 && threadIdx.x == 0) g_min_bits = 0xFFFFFFFFu;
    if (warp >= P + R) return;
    const float4* src4;
    uint2* dst2;
    if (warp < P) {
        src4 = (const float4*)(x + (size_t)warp * DIM);
        dst2 = (uint2*)(g_A + (size_t)warp * DIM);
    } else {
        int r = warp - P;
        src4 = (const float4*)(y + (size_t)r * DIM);
        dst2 = (uint2*)(g_B + (size_t)r * DIM);
    }
    float acc = 0.f;
#pragma unroll
    for (int j = 0; j < 4; j++) {
        float4 v = src4[lane + j * 32];
        acc += v.x * v.x + v.y * v.y + v.z * v.z + v.w * v.w;
        __nv_bfloat162 lo = __floats2bfloat162_rn(v.x, v.y);
        __nv_bfloat162 hi = __floats2bfloat162_rn(v.z, v.w);
        uint2 u;
        u.x = *reinterpret_cast<unsigned int*>(&lo);
        u.y = *reinterpret_cast<unsigned int*>(&hi);
        dst2[lane + j * 32] = u;
    }
#pragma unroll
    for (int off = 16; off > 0; off >>= 1)
        acc += __shfl_xor_sync(0xFFFFFFFFu, acc, off);
    if (lane == 0) {
        if (warp < P) g_xn[warp] = acc;
        else          g_yn[warp - P] = acc;
    }
}

// ------------- kernel 1: bf16 mma.sync GEMM + min reduction -------------
// 128x128 CTA tile, 8 warps in 4(M) x 2(N), 32x64 per warp, 2 CTAs/SM.
// Grid launched bm-fastest: a wave of 296 CTAs covers all 16 bm values x ~18
// bn values, so A (2MB) and the active B slice (~2.4MB) stay L2-resident and
// each B byte is fetched from DRAM exactly once (64MB total vs 1GB before).
__global__ void __launch_bounds__(256, 2)
min_dist_mma_kernel(int P, int R) {
    extern __shared__ char smem[];
    uint32_t sbase = smem_u32(smem);
    const int tid = threadIdx.x;
    const int lane = tid & 31;
    const int warp = tid >> 5;
    const int wm = warp & 3;          // 0..3 : M direction (32 rows each)
    const int wn = warp >> 2;         // 0..1 : N direction (64 cols each)
    const int bm = blockIdx.x * BM;   // bm fastest
    const int bn = blockIdx.y * BN;

    // Stage norms in SMEM for the epilogue.
    if (tid < 128)       ((float*)(smem + SOFF_XN))[tid] = g_xn[bm + tid];
    else                 ((float*)(smem + SOFF_YN))[tid - 128] = g_yn[bn + tid - 128];

    float acc[2][8][4];
#pragma unroll
    for (int i = 0; i < 2; i++)
#pragma unroll
        for (int j = 0; j < 8; j++)
#pragma unroll
            for (int r = 0; r < 4; r++) acc[i][j][r] = 0.f;

    // Prologue: prefetch chunks 0,1.
    load_stage(sbase, 0, 0, bm, bn, tid);
    asm volatile("cp.async.commit_group;" ::: "memory");
    load_stage(sbase, 1, BK, bm, bn, tid);
    asm volatile("cp.async.commit_group;" ::: "memory");

    const int lrow = lane & 15;
    const int lcol = (lane >> 4) << 4;   // 0 or 16 bytes

    for (int k = 0; k < NCHUNK; k++) {
        const int s = k % STAGES;
        asm volatile("cp.async.wait_group 1;" ::: "memory");
        __syncthreads();
        if (k + 2 < NCHUNK)
            load_stage(sbase, (k + 2) % STAGES, (k + 2) * BK, bm, bn, tid);
        asm volatile("cp.async.commit_group;" ::: "memory");

        const uint32_t a0 = sbase + s * STAGE_BYTES;
        const uint32_t b0 = a0 + A_BYTES;
#pragma unroll
        for (int kk = 0; kk < 4; kk++) {          // 4 x k16 steps per chunk
            const int colb = kk * 32 + lcol;
            uint32_t af[2][4];
#pragma unroll
            for (int mi = 0; mi < 2; mi++) {
                int row = wm * 32 + mi * 16 + lrow;
                ldsm_x4(af[mi][0], af[mi][1], af[mi][2], af[mi][3],
                        a0 + swz(row * 128 + colb));
            }
            uint32_t bf[8][2];
#pragma unroll
            for (int ni2 = 0; ni2 < 4; ni2++) {   // each x4 covers 2 n8 tiles
                int row = wn * 64 + ni2 * 16 + lrow;
                uint32_t r0, r1, r2, r3;
                ldsm_x4(r0, r1, r2, r3, b0 + swz(row * 128 + colb));
                bf[ni2 * 2 + 0][0] = r0; bf[ni2 * 2 + 0][1] = r2;
                bf[ni2 * 2 + 1][0] = r1; bf[ni2 * 2 + 1][1] = r3;
            }
#pragma unroll
            for (int mi = 0; mi < 2; mi++)
#pragma unroll
                for (int ni = 0; ni < 8; ni++)
                    mma_bf16(acc[mi][ni], af[mi], bf[ni][0], bf[ni][1]);
        }
    }

    // Epilogue: sq = xn + yn - 2*dot; per-fragment min.
    const float* xs = (const float*)(smem + SOFF_XN);
    const float* ys = (const float*)(smem + SOFF_YN);
    float m = 3.4e38f;
#pragma unroll
    for (int mi = 0; mi < 2; mi++) {
        float x0 = xs[wm * 32 + mi * 16 + (lane >> 2)];
        float x1 = xs[wm * 32 + mi * 16 + (lane >> 2) + 8];
#pragma unroll
        for (int ni = 0; ni < 8; ni++) {
            float y0 = ys[wn * 64 + ni * 8 + (lane & 3) * 2];
            float y1 = ys[wn * 64 + ni * 8 + (lane & 3) * 2 + 1];
            m = fminf(m, fmaf(-2.0f, acc[mi][ni][0], x0 + y0));
            m = fminf(m, fmaf(-2.0f, acc[mi][ni][1], x0 + y1));
            m = fminf(m, fmaf(-2.0f, acc[mi][ni][2], x1 + y0));
            m = fminf(m, fmaf(-2.0f, acc[mi][ni][3], x1 + y1));
        }
    }
#pragma unroll
    for (int off = 16; off > 0; off >>= 1)
        m = fminf(m, __shfl_xor_sync(0xFFFFFFFFu, m, off));

    // Block-level min: 8 warp partials -> 1 atomic per CTA.
    float* red = (float*)(smem + SOFF_RED);
    if (lane == 0) red[warp] = m;
    __syncthreads();
    if (tid == 0) {
        float bmv = red[0];
#pragma unroll
        for (int w = 1; w < 8; w++) bmv = fminf(bmv, red[w]);
        atomicMin(&g_min_bits, enc_f(bmv));
    }
}

// ------------- kernel 2: finalize -------------
__global__ void finalize_kernel(float* __restrict__ out) {
    out[0] = sqrtf(fmaxf(dec_f(g_min_bits), 0.0f));
}

extern "C" void kernel_launch(void* const* d_in, const int* in_sizes, int n_in,
                              void* d_out, int out_size) {
    const float* x = (const float*)d_in[0];  // [1, P, 512] fp32
    const float* y = (const float*)d_in[1];  // [1, R, 512] fp32
    int P = in_sizes[0] / DIM;
    int R = in_sizes[1] / DIM;

    int rows = P + R;  // one warp per row
    prep_kernel<<<(rows * 32 + 255) / 256, 256>>>(x, y, P, R);

    cudaFuncSetAttribute(min_dist_mma_kernel,
                         cudaFuncAttributeMaxDynamicSharedMemorySize, SMEM_BYTES);
    dim3 grid(P / BM, R / BN);  // (16, 512): bm fastest for B-tile L2 reuse
    min_dist_mma_kernel<<<grid, 256, SMEM_BYTES>>>(P, R);

    finalize_kernel<<<1, 1>>>((float*)d_out);
}

// round 14
// speedup vs baseline: 1.1471x; 1.0650x over previous
#include <cuda_runtime.h>
#include <cuda_bf16.h>
#include <math.h>
#include <stdint.h>

#define DIM 512
#define P_MAX 2048
#define R_MAX 65536
#define BM 128
#define BN 128
#define BK 64                 // bf16 elems per chunk = 128 bytes/row
#define NCHUNK (DIM / BK)     // 8
#define STAGES 3
#define A_BYTES (BM * 128)    // 16384
#define B_BYTES (BN * 128)    // 16384
#define STAGE_BYTES (A_BYTES + B_BYTES)          // 32768
#define SOFF_XN (STAGES * STAGE_BYTES)           // 98304
#define SOFF_YN (SOFF_XN + BM * 4)
#define SOFF_MBAR (SOFF_YN + BN * 4)             // full[3]@+0, empty[3]@+24
#define SMEM_BYTES (SOFF_MBAR + 64)              // 99392 -> 2 CTAs/SM

// Scratch (no allocations allowed)
__device__ __nv_bfloat16 g_A[P_MAX * DIM];   // 2 MB
__device__ __nv_bfloat16 g_B[R_MAX * DIM];   // 64 MB
__device__ float g_xn[P_MAX];
__device__ float g_yn[R_MAX];
__device__ unsigned int g_min_bits;

// ---------------- helpers ----------------
__device__ __forceinline__ unsigned int enc_f(float f) {
    unsigned int u = __float_as_uint(f);
    return (u & 0x80000000u) ? ~u : (u | 0x80000000u);
}
__device__ __forceinline__ float dec_f(unsigned int u) {
    return (u & 0x80000000u) ? __uint_as_float(u & 0x7FFFFFFFu)
                             : __uint_as_float(~u);
}
__device__ __forceinline__ uint32_t smem_u32(const void* p) {
    uint32_t a;
    asm("{ .reg .u64 t; cvta.to.shared.u64 t, %1; cvt.u32.u64 %0, t; }"
        : "=r"(a) : "l"(p));
    return a;
}
__device__ __forceinline__ void cp16(uint32_t dst, const void* src) {
    asm volatile("cp.async.cg.shared.global [%0], [%1], 16;"
                 :: "r"(dst), "l"(src) : "memory");
}
__device__ __forceinline__ uint32_t swz(uint32_t off) {
    return off ^ ((off >> 3) & 0x70);   // SW128 pattern on 128B rows
}
__device__ __forceinline__ void ldsm_x4(uint32_t& r0, uint32_t& r1,
                                        uint32_t& r2, uint32_t& r3,
                                        uint32_t addr) {
    asm volatile("ldmatrix.sync.aligned.m8n8.x4.shared.b16 {%0,%1,%2,%3}, [%4];"
                 : "=r"(r0), "=r"(r1), "=r"(r2), "=r"(r3) : "r"(addr));
}
__device__ __forceinline__ void mma_bf16(float* c, const uint32_t* a,
                                         uint32_t b0, uint32_t b1) {
    asm volatile(
        "mma.sync.aligned.m16n8k16.row.col.f32.bf16.bf16.f32 "
        "{%0,%1,%2,%3}, {%4,%5,%6,%7}, {%8,%9}, {%0,%1,%2,%3};"
        : "+f"(c[0]), "+f"(c[1]), "+f"(c[2]), "+f"(c[3])
        : "r"(a[0]), "r"(a[1]), "r"(a[2]), "r"(a[3]), "r"(b0), "r"(b1));
}
__device__ __forceinline__ void mbar_init(uint32_t mbar, uint32_t cnt) {
    asm volatile("mbarrier.init.shared.b64 [%0], %1;" :: "r"(mbar), "r"(cnt) : "memory");
}
__device__ __forceinline__ void mbar_arrive(uint32_t mbar) {
    asm volatile("mbarrier.arrive.release.cta.shared.b64 _, [%0];"
                 :: "r"(mbar) : "memory");
}
__device__ __forceinline__ void mbar_wait(uint32_t mbar, int parity) {
    asm volatile(
        "{\n\t.reg .pred P;\n\t"
        "LW%=:\n\t"
        "mbarrier.try_wait.parity.acquire.cta.shared::cta.b64 P, [%0], %1;\n\t"
        "@!P bra LW%=;\n\t}"
        :: "r"(mbar), "r"(parity) : "memory");
}
__device__ __forceinline__ void cpasync_arrive(uint32_t mbar) {
    asm volatile("cp.async.mbarrier.arrive.noinc.shared.b64 [%0];"
                 :: "r"(mbar) : "memory");
}

// Load one K-chunk (A:128x64, B:128x64 bf16) into SW128-swizzled SMEM.
// 2048 x 16B units over 256 threads = 8 cp.async each.
__device__ __forceinline__ void load_stage(uint32_t sbase, int s, int k0,
                                           int bm, int bn, int tid) {
    uint32_t a0 = sbase + s * STAGE_BYTES;
    uint32_t b0 = a0 + A_BYTES;
#pragma unroll
    for (int i = 0; i < 4; i++) {            // A: 1024 units
        int u = tid + i * 256;
        int row = u >> 3, c = u & 7;
        uint32_t sw = swz(row * 128 + c * 16);
        cp16(a0 + sw, g_A + (size_t)(bm + row) * DIM + k0 + c * 8);
    }
#pragma unroll
    for (int i = 0; i < 4; i++) {            // B: 1024 units
        int u = tid + i * 256;
        int row = u >> 3, c = u & 7;
        uint32_t sw = swz(row * 128 + c * 16);
        cp16(b0 + sw, g_B + (size_t)(bn + row) * DIM + k0 + c * 8);
    }
}

// ------------- kernel 0: convert to bf16, fp32 norms, reset min -------------
__global__ void prep_kernel(const float* __restrict__ x,
                            const float* __restrict__ y, int P, int R) {
    int warp = (blockIdx.x * blockDim.x + threadIdx.x) >> 5;
    int lane = threadIdx.x & 31;
    if (blockIdx.x == 0 && threadIdx.x == 0) g_min_bits = 0xFFFFFFFFu;
    if (warp >= P + R) return;
    const float4* src4;
    uint2* dst2;
    if (warp < P) {
        src4 = (const float4*)(x + (size_t)warp * DIM);
        dst2 = (uint2*)(g_A + (size_t)warp * DIM);
    } else {
        int r = warp - P;
        src4 = (const float4*)(y + (size_t)r * DIM);
        dst2 = (uint2*)(g_B + (size_t)r * DIM);
    }
    float acc = 0.f;
#pragma unroll
    for (int j = 0; j < 4; j++) {
        float4 v = src4[lane + j * 32];
        acc += v.x * v.x + v.y * v.y + v.z * v.z + v.w * v.w;
        __nv_bfloat162 lo = __floats2bfloat162_rn(v.x, v.y);
        __nv_bfloat162 hi = __floats2bfloat162_rn(v.z, v.w);
        uint2 u;
        u.x = *reinterpret_cast<unsigned int*>(&lo);
        u.y = *reinterpret_cast<unsigned int*>(&hi);
        dst2[lane + j * 32] = u;
    }
#pragma unroll
    for (int off = 16; off > 0; off >>= 1)
        acc += __shfl_xor_sync(0xFFFFFFFFu, acc, off);
    if (lane == 0) {
        if (warp < P) g_xn[warp] = acc;
        else          g_yn[warp - P] = acc;
    }
}

// ------------- kernel 1: bf16 mma.sync GEMM, mbarrier pipeline -------------
// 128x128 CTA tile, 8 warps in 4(M) x 2(N), 32x64 per warp, 2 CTAs/SM.
// No __syncthreads in the mainloop: full[s] (cnt 256, cp.async completion
// from all threads) gates reads; empty[s] (cnt 8, one arrive per warp at its
// ldsm-retire proof point) gates stage overwrite. The per-warp mma tail runs
// after the empty arrive, so joins are on "reads done", not "chunk done".
__global__ void __launch_bounds__(256, 2)
min_dist_mma_kernel(int P, int R) {
    extern __shared__ char smem[];
    uint32_t sbase = smem_u32(smem);
    const int tid = threadIdx.x;
    const int lane = tid & 31;
    const int warp = tid >> 5;
    const int wm = warp & 3;          // 0..3 : M direction (32 rows each)
    const int wn = warp >> 2;         // 0..1 : N direction (64 cols each)
    const int bm = blockIdx.y * BM;
    const int bn = blockIdx.x * BN;

    const uint32_t mb_full = sbase + SOFF_MBAR;        // +8*s
    const uint32_t mb_empty = sbase + SOFF_MBAR + 24;  // +8*s

    if (tid == 0) {
#pragma unroll
        for (int s = 0; s < STAGES; s++) {
            mbar_init(mb_full + 8 * s, 256);
            mbar_init(mb_empty + 8 * s, 8);
        }
    }
    // Stage norms in SMEM for the epilogue.
    if (tid < 128)       ((float*)(smem + SOFF_XN))[tid] = g_xn[bm + tid];
    else                 ((float*)(smem + SOFF_YN))[tid - 128] = g_yn[bn + tid - 128];
    __syncthreads();   // mbarriers initialized + norms staged

    // Prologue: fill all 3 stages.
#pragma unroll
    for (int c = 0; c < STAGES; c++) {
        load_stage(sbase, c, c * BK, bm, bn, tid);
        cpasync_arrive(mb_full + 8 * c);
    }

    float acc[2][8][4];
#pragma unroll
    for (int i = 0; i < 2; i++)
#pragma unroll
        for (int j = 0; j < 8; j++)
#pragma unroll
            for (int r = 0; r < 4; r++) acc[i][j][r] = 0.f;

    const int lrow = lane & 15;
    const int lcol = (lane >> 4) << 4;   // 0 or 16 bytes

#pragma unroll
    for (int k = 0; k < NCHUNK; k++) {
        const int s = k % STAGES;                 // compile-time (unrolled)
        const int ph = (k / STAGES) & 1;          // compile-time parity
        mbar_wait(mb_full + 8 * s, ph);           // chunk k visible (all thr)

        const uint32_t a0 = sbase + s * STAGE_BYTES;
        const uint32_t b0 = a0 + A_BYTES;
#pragma unroll
        for (int kk = 0; kk < 4; kk++) {          // 4 x k16 steps per chunk
            const int colb = kk * 32 + lcol;
            uint32_t af[2][4];
#pragma unroll
            for (int mi = 0; mi < 2; mi++) {
                int row = wm * 32 + mi * 16 + lrow;
                ldsm_x4(af[mi][0], af[mi][1], af[mi][2], af[mi][3],
                        a0 + swz(row * 128 + colb));
            }
            uint32_t bf[8][2];
#pragma unroll
            for (int ni2 = 0; ni2 < 4; ni2++) {   // each x4 covers 2 n8 tiles
                int row = wn * 64 + ni2 * 16 + lrow;
                uint32_t r0, r1, r2, r3;
                ldsm_x4(r0, r1, r2, r3, b0 + swz(row * 128 + colb));
                bf[ni2 * 2 + 0][0] = r0; bf[ni2 * 2 + 0][1] = r2;
                bf[ni2 * 2 + 1][0] = r1; bf[ni2 * 2 + 1][1] = r3;
            }
            if (kk == 3) {
                // Proof mmas: consume a register from EVERY ldsm of this final
                // step -> warp's smem reads provably retired, then arrive.
                mma_bf16(acc[0][0], af[0], bf[0][0], bf[0][1]);  // a0, b-ldsm0
                mma_bf16(acc[0][2], af[0], bf[2][0], bf[2][1]);  // b-ldsm1
                mma_bf16(acc[0][4], af[0], bf[4][0], bf[4][1]);  // b-ldsm2
                mma_bf16(acc[0][6], af[0], bf[6][0], bf[6][1]);  // b-ldsm3
                mma_bf16(acc[1][0], af[1], bf[0][0], bf[0][1]);  // a-ldsm1
                if (lane == 0) mbar_arrive(mb_empty + 8 * s);    // reads done
                mma_bf16(acc[0][1], af[0], bf[1][0], bf[1][1]);
                mma_bf16(acc[0][3], af[0], bf[3][0], bf[3][1]);
                mma_bf16(acc[0][5], af[0], bf[5][0], bf[5][1]);
                mma_bf16(acc[0][7], af[0], bf[7][0], bf[7][1]);
#pragma unroll
                for (int ni = 1; ni < 8; ni++)
                    mma_bf16(acc[1][ni], af[1], bf[ni][0], bf[ni][1]);
            } else {
#pragma unroll
                for (int mi = 0; mi < 2; mi++)
#pragma unroll
                    for (int ni = 0; ni < 8; ni++)
                        mma_bf16(acc[mi][ni], af[mi], bf[ni][0], bf[ni][1]);
            }
        }

        // Refill this stage with chunk k+3 once all 8 warps finished reading.
        if (k + STAGES < NCHUNK) {
            mbar_wait(mb_empty + 8 * s, ph);
            load_stage(sbase, s, (k + STAGES) * BK, bm, bn, tid);
            cpasync_arrive(mb_full + 8 * s);
        }
    }

    // Epilogue: sq = xn + yn - 2*dot; per-fragment min.
    const float* xs = (const float*)(smem + SOFF_XN);
    const float* ys = (const float*)(smem + SOFF_YN);
    float m = 3.4e38f;
#pragma unroll
    for (int mi = 0; mi < 2; mi++) {
        float x0 = xs[wm * 32 + mi * 16 + (lane >> 2)];
        float x1 = xs[wm * 32 + mi * 16 + (lane >> 2) + 8];
#pragma unroll
        for (int ni = 0; ni < 8; ni++) {
            float y0 = ys[wn * 64 + ni * 8 + (lane & 3) * 2];
            float y1 = ys[wn * 64 + ni * 8 + (lane & 3) * 2 + 1];
            m = fminf(m, fmaf(-2.0f, acc[mi][ni][0], x0 + y0));
            m = fminf(m, fmaf(-2.0f, acc[mi][ni][1], x0 + y1));
            m = fminf(m, fmaf(-2.0f, acc[mi][ni][2], x1 + y0));
            m = fminf(m, fmaf(-2.0f, acc[mi][ni][3], x1 + y1));
        }
    }
#pragma unroll
    for (int off = 16; off > 0; off >>= 1)
        m = fminf(m, __shfl_xor_sync(0xFFFFFFFFu, m, off));
    if (lane == 0) atomicMin(&g_min_bits, enc_f(m));
}

// ------------- kernel 2: finalize -------------
__global__ void finalize_kernel(float* __restrict__ out) {
    out[0] = sqrtf(fmaxf(dec_f(g_min_bits), 0.0f));
}

extern "C" void kernel_launch(void* const* d_in, const int* in_sizes, int n_in,
                              void* d_out, int out_size) {
    const float* x = (const float*)d_in[0];  // [1, P, 512] fp32
    const float* y = (const float*)d_in[1];  // [1, R, 512] fp32
    int P = in_sizes[0] / DIM;
    int R = in_sizes[1] / DIM;

    int rows = P + R;  // one warp per row
    prep_kernel<<<(rows * 32 + 255) / 256, 256>>>(x, y, P, R);

    cudaFuncSetAttribute(min_dist_mma_kernel,
                         cudaFuncAttributeMaxDynamicSharedMemorySize, SMEM_BYTES);
    dim3 grid(R / BN, P / BM);  // (512, 16) = 8192 CTAs, bn fastest (champion)
    min_dist_mma_kernel<<<grid, 256, SMEM_BYTES>>>(P, R);

    finalize_kernel<<<1, 1>>>((float*)d_out);
}